// round 4
// baseline (speedup 1.0000x reference)
#include <cuda_runtime.h>

// SKA: out[b, g*8+cw, h, w] = sum_{i,j} x[b, g*8+cw, h+i-1, w+j-1] * w[b, cw, i*3+j, h, w]
// x: (8,64,128,128) f32, w: (8,8,9,128,128) f32, out: (8,64,128,128) f32
//
// R4: latency-bound fix. Weights staged in SMEM (36KB/block, loaded once with
// full MLP) instead of 36 regs/thread; halos via warp shuffle (warp spans the
// whole 128-wide row); 2 group channels per pass for dual independent FMA
// chains per weight load. Regs ~38 -> 6 blocks/SM (smem-limited), occ ~75%.

#define SKA_H 128
#define SKA_W 128
#define SKA_C 64
#define SKA_CW 8
#define SKA_HW (SKA_H * SKA_W)

__global__ __launch_bounds__(256, 6)
void SKA_44830868635847_kernel(const float* __restrict__ x,
                               const float* __restrict__ wgt,
                               float* __restrict__ out) {
    __shared__ float w_s[SKA_CW * 9 * SKA_W];  // 9216 floats = 36 KB

    const int tid  = threadIdx.x;
    const int lane = tid & 31;
    const int w0   = lane << 2;     // 0,4,...,124 (warp spans full row)
    const int cw   = tid >> 5;      // warp id = weight channel
    const int h    = blockIdx.x;
    const int b    = blockIdx.y;

    // ---- Stage weights for this (b, h): 72 rows x 128 floats, coalesced ----
    {
        const float* wb = wgt + (long)b * (SKA_CW * 9) * SKA_HW + h * SKA_W;
        #pragma unroll
        for (int it = 0; it < 9; it++) {
            const int idx = tid * 4 + it * 1024;       // element index in [0, 9216)
            const int row = idx >> 7;                  // (cw*9 + k)
            const int col = idx & 127;
            const float4 v = *reinterpret_cast<const float4*>(wb + (long)row * SKA_HW + col);
            *reinterpret_cast<float4*>(&w_s[idx]) = v;
        }
    }
    __syncthreads();

    const float* xb = x + (long)(b * SKA_C) * SKA_HW;
    float* ob = out + (long)(b * SKA_C) * SKA_HW;
    const unsigned FULL = 0xFFFFFFFFu;

    #pragma unroll 1
    for (int p = 0; p < 4; p++) {
        const int ca = (2 * p) * SKA_CW + cw;
        const int cb = (2 * p + 1) * SKA_CW + cw;
        const float* xa = xb + (long)ca * SKA_HW;
        const float* xc = xb + (long)cb * SKA_HW;

        float aa0 = 0.f, aa1 = 0.f, aa2 = 0.f, aa3 = 0.f;
        float ba0 = 0.f, ba1 = 0.f, ba2 = 0.f, ba3 = 0.f;

        #pragma unroll
        for (int i = 0; i < 3; i++) {
            const int hh = h + i - 1;
            float a0, a1, a2, a3, a4, a5;
            float b0, b1, b2, b3, b4, b5;
            if (hh < 0 || hh >= SKA_H) {               // warp-uniform branch
                a0 = a1 = a2 = a3 = a4 = a5 = 0.f;
                b0 = b1 = b2 = b3 = b4 = b5 = 0.f;
            } else {
                const float4 ma = *reinterpret_cast<const float4*>(xa + hh * SKA_W + w0);
                const float4 mb = *reinterpret_cast<const float4*>(xc + hh * SKA_W + w0);
                a1 = ma.x; a2 = ma.y; a3 = ma.z; a4 = ma.w;
                b1 = mb.x; b2 = mb.y; b3 = mb.z; b4 = mb.w;
                a0 = __shfl_up_sync(FULL, a4, 1);   if (lane == 0)  a0 = 0.f;
                a5 = __shfl_down_sync(FULL, a1, 1); if (lane == 31) a5 = 0.f;
                b0 = __shfl_up_sync(FULL, b4, 1);   if (lane == 0)  b0 = 0.f;
                b5 = __shfl_down_sync(FULL, b1, 1); if (lane == 31) b5 = 0.f;
            }

            const float* wrow = &w_s[(cw * 9 + i * 3) * SKA_W + w0];
            {
                const float4 wk = *reinterpret_cast<const float4*>(wrow);            // j=0
                aa0 = fmaf(wk.x, a0, aa0); aa1 = fmaf(wk.y, a1, aa1);
                aa2 = fmaf(wk.z, a2, aa2); aa3 = fmaf(wk.w, a3, aa3);
                ba0 = fmaf(wk.x, b0, ba0); ba1 = fmaf(wk.y, b1, ba1);
                ba2 = fmaf(wk.z, b2, ba2); ba3 = fmaf(wk.w, b3, ba3);
            }
            {
                const float4 wk = *reinterpret_cast<const float4*>(wrow + SKA_W);    // j=1
                aa0 = fmaf(wk.x, a1, aa0); aa1 = fmaf(wk.y, a2, aa1);
                aa2 = fmaf(wk.z, a3, aa2); aa3 = fmaf(wk.w, a4, aa3);
                ba0 = fmaf(wk.x, b1, ba0); ba1 = fmaf(wk.y, b2, ba1);
                ba2 = fmaf(wk.z, b3, ba2); ba3 = fmaf(wk.w, b4, ba3);
            }
            {
                const float4 wk = *reinterpret_cast<const float4*>(wrow + 2 * SKA_W); // j=2
                aa0 = fmaf(wk.x, a2, aa0); aa1 = fmaf(wk.y, a3, aa1);
                aa2 = fmaf(wk.z, a4, aa2); aa3 = fmaf(wk.w, a5, aa3);
                ba0 = fmaf(wk.x, b2, ba0); ba1 = fmaf(wk.y, b3, ba1);
                ba2 = fmaf(wk.z, b4, ba2); ba3 = fmaf(wk.w, b5, ba3);
            }
        }

        float4 oa; oa.x = aa0; oa.y = aa1; oa.z = aa2; oa.w = aa3;
        float4 obv; obv.x = ba0; obv.y = ba1; obv.z = ba2; obv.w = ba3;
        *reinterpret_cast<float4*>(ob + (long)ca * SKA_HW + h * SKA_W + w0) = oa;
        *reinterpret_cast<float4*>(ob + (long)cb * SKA_HW + h * SKA_W + w0) = obv;
    }
}

extern "C" void kernel_launch(void* const* d_in, const int* in_sizes, int n_in,
                              void* d_out, int out_size) {
    const float* x = (const float*)d_in[0];
    const float* w = (const float*)d_in[1];
    float* out = (float*)d_out;
    (void)in_sizes; (void)n_in; (void)out_size;

    dim3 grid(SKA_H, 8);   // (h, b)
    dim3 block(256);       // 8 warps = 8 cw; 32 lanes x 4 = W
    SKA_44830868635847_kernel<<<grid, block>>>(x, w, out);
}

// round 6
// speedup vs baseline: 1.2567x; 1.2567x over previous
#include <cuda_runtime.h>

// SKA: out[b, g*8+cw, h, w] = sum_{i,j} x[b, g*8+cw, h+i-1, w+j-1] * w[b, cw, i*3+j, h, w]
// x: (8,64,128,128) f32, w: (8,8,9,128,128) f32, out: (8,64,128,128) f32
//
// R5: single-wave layout. 128-thread blocks (4 warps), grid=1024=(h,b).
// Each warp handles TWO cw channels sequentially (cw = wid and wid+4).
// At ~62 regs -> 8 blocks/SM resident -> capacity 1184 >= 1024 blocks:
// the whole kernel runs as ONE wave (no tail wave, no wave transition).
// R3 body kept: 9 weight float4 in registers reused across 8 group channels,
// scalar-LDG halos (L1 hits), fully unrolled g loop for load front-batching.

#define SKA_H 128
#define SKA_W 128
#define SKA_C 64
#define SKA_CW 8
#define SKA_HW (SKA_H * SKA_W)

__global__ __launch_bounds__(128, 8)
void SKA_44830868635847_kernel(const float* __restrict__ x,
                               const float* __restrict__ wgt,
                               float* __restrict__ out) {
    const int tid  = threadIdx.x;
    const int lane = tid & 31;
    const int w0   = lane << 2;    // 0,4,...,124 (warp spans the full row)
    const int wid  = tid >> 5;     // 0..3
    const int h    = blockIdx.x;   // 0..127
    const int b    = blockIdx.y;   // 0..7

    const float* xb = x + (long)(b * SKA_C) * SKA_HW;
    float* ob = out + (long)(b * SKA_C) * SKA_HW;

    #pragma unroll 1
    for (int half = 0; half < 2; half++) {
        const int cw = wid + half * 4;   // weight channel for this pass

        // 9 per-position weight vectors for (b, cw, h, w0..w0+3), in registers,
        // reused across all 8 group channels.
        float4 wv[9];
        const float* wp = wgt + ((long)(b * SKA_CW + cw) * 9 * SKA_H + h) * SKA_W + w0;
        #pragma unroll
        for (int k = 0; k < 9; k++) {
            wv[k] = *reinterpret_cast<const float4*>(wp + (long)k * SKA_HW);
        }

        #pragma unroll
        for (int g = 0; g < 8; g++) {
            const int c = g * SKA_CW + cw;
            const float* xc = xb + (long)c * SKA_HW;

            float acc0 = 0.f, acc1 = 0.f, acc2 = 0.f, acc3 = 0.f;

            #pragma unroll
            for (int i = 0; i < 3; i++) {
                const int hh = h + i - 1;
                float r0, r1, r2, r3, r4, r5;
                if (hh < 0 || hh >= SKA_H) {           // warp-uniform
                    r0 = r1 = r2 = r3 = r4 = r5 = 0.f;
                } else {
                    const float* row = xc + hh * SKA_W + w0;
                    const float4 m = *reinterpret_cast<const float4*>(row);
                    r1 = m.x; r2 = m.y; r3 = m.z; r4 = m.w;
                    r0 = (w0 == 0)         ? 0.f : row[-1];
                    r5 = (w0 + 4 >= SKA_W) ? 0.f : row[4];
                }
                {
                    const float4 wk = wv[i * 3 + 0];   // j=0
                    acc0 = fmaf(wk.x, r0, acc0);
                    acc1 = fmaf(wk.y, r1, acc1);
                    acc2 = fmaf(wk.z, r2, acc2);
                    acc3 = fmaf(wk.w, r3, acc3);
                }
                {
                    const float4 wk = wv[i * 3 + 1];   // j=1
                    acc0 = fmaf(wk.x, r1, acc0);
                    acc1 = fmaf(wk.y, r2, acc1);
                    acc2 = fmaf(wk.z, r3, acc2);
                    acc3 = fmaf(wk.w, r4, acc3);
                }
                {
                    const float4 wk = wv[i * 3 + 2];   // j=2
                    acc0 = fmaf(wk.x, r2, acc0);
                    acc1 = fmaf(wk.y, r3, acc1);
                    acc2 = fmaf(wk.z, r4, acc2);
                    acc3 = fmaf(wk.w, r5, acc3);
                }
            }

            float4 o;
            o.x = acc0; o.y = acc1; o.z = acc2; o.w = acc3;
            *reinterpret_cast<float4*>(ob + (long)c * SKA_HW + h * SKA_W + w0) = o;
        }
    }
}

extern "C" void kernel_launch(void* const* d_in, const int* in_sizes, int n_in,
                              void* d_out, int out_size) {
    const float* x = (const float*)d_in[0];
    const float* w = (const float*)d_in[1];
    float* out = (float*)d_out;
    (void)in_sizes; (void)n_in; (void)out_size;

    dim3 grid(SKA_H, 8);   // (h, b): 1024 blocks, all resident in one wave
    dim3 block(128);       // 4 warps; each warp covers cw=wid and wid+4
    SKA_44830868635847_kernel<<<grid, block>>>(x, w, out);
}